// round 15
// baseline (speedup 1.0000x reference)
#include <cuda_runtime.h>
#include <math.h>

#define H    256
#define H2   512
#define SEQ  256
#define NL   4
#define VOC  50257
#define TPB  512
#define NWARP 16

#define GEMV_GRID 148
#define GEMV_TOTW (GEMV_GRID * NWARP)   // 2368
#define GEMV_ITERS 3                    // 3*2368*8 = 56832 >= VOC

// ---------------- scratch (device globals; no allocation allowed) ----------
__device__ __align__(16) float  g_attn_logits[SEQ];
__device__ __align__(16) float  g_gh[NL * 3 * H];    // h@whh.T + bhh
__device__ __align__(16) float  g_xbuf[2][H];
__device__ __align__(16) float2 g_red[GEMV_GRID];
__device__ __align__(16) unsigned g_f4[GEMV_GRID];   // gemv (m,s)-published flags

// ---------------- PDL helpers -----------------------------------------------
__device__ __forceinline__ void pdl_wait() {
    asm volatile("griddepcontrol.wait;" ::: "memory");
}
__device__ __forceinline__ void pdl_trigger() {
    asm volatile("griddepcontrol.launch_dependents;" ::: "memory");
}

// ---------------- math helpers ----------------------------------------------
__device__ __forceinline__ float dot4f(float4 a, float4 b) {
    return fmaf(a.x, b.x, fmaf(a.y, b.y, fmaf(a.z, b.z, a.w * b.w)));
}
__device__ __forceinline__ float wredsum(float v) {
    #pragma unroll
    for (int o = 16; o; o >>= 1) v += __shfl_xor_sync(0xffffffffu, v, o);
    return v;
}
__device__ __forceinline__ float red4(float d0, float d1, float d2, float d3, int lane) {
    bool h16 = (lane & 16) != 0, h8 = (lane & 8) != 0;
    float k0 = (h16 ? d2 : d0) + __shfl_xor_sync(0xffffffffu, h16 ? d0 : d2, 16);
    float k1 = (h16 ? d3 : d1) + __shfl_xor_sync(0xffffffffu, h16 ? d1 : d3, 16);
    float v  = (h8 ? k1 : k0) + __shfl_xor_sync(0xffffffffu, h8 ? k0 : k1, 8);
    v += __shfl_xor_sync(0xffffffffu, v, 4);
    v += __shfl_xor_sync(0xffffffffu, v, 2);
    v += __shfl_xor_sync(0xffffffffu, v, 1);
    return v;
}
__device__ __forceinline__ float red8(const float* d, int lane) {
    bool h16 = (lane & 16) != 0, h8 = (lane & 8) != 0, h4b = (lane & 4) != 0;
    float k0 = (h16 ? d[4] : d[0]) + __shfl_xor_sync(0xffffffffu, h16 ? d[0] : d[4], 16);
    float k1 = (h16 ? d[5] : d[1]) + __shfl_xor_sync(0xffffffffu, h16 ? d[1] : d[5], 16);
    float k2 = (h16 ? d[6] : d[2]) + __shfl_xor_sync(0xffffffffu, h16 ? d[2] : d[6], 16);
    float k3 = (h16 ? d[7] : d[3]) + __shfl_xor_sync(0xffffffffu, h16 ? d[3] : d[7], 16);
    float m0 = (h8 ? k2 : k0) + __shfl_xor_sync(0xffffffffu, h8 ? k0 : k2, 8);
    float m1 = (h8 ? k3 : k1) + __shfl_xor_sync(0xffffffffu, h8 ? k1 : k3, 8);
    float v  = (h4b ? m1 : m0) + __shfl_xor_sync(0xffffffffu, h4b ? m0 : m1, 4);
    v += __shfl_xor_sync(0xffffffffu, v, 2);
    v += __shfl_xor_sync(0xffffffffu, v, 1);
    return v;
}

// ====================== K1: attention logits + gh (grid 80) =================
__global__ void __launch_bounds__(TPB, 1)
k_logits_gh(const int* __restrict__ token,
            const float* __restrict__ hidden,
            const float* __restrict__ emb,
            const float* __restrict__ attn_w,
            const float* __restrict__ attn_b,
            const float* __restrict__ gru_whh,
            const float* __restrict__ gru_bhh)
{
    const int tid = threadIdx.x, bid = blockIdx.x;
    const int wid = tid >> 5, lane = tid & 31;
    __shared__ __align__(16) float s_in[H2];

    if (bid < 16) {
        const int tok = token[0];
        const float* erow = emb + (size_t)tok * H;
        s_in[tid] = (tid < H) ? __ldg(erow + tid) : __ldg(hidden + tid - H);
        __syncthreads();
        const float4* in4 = (const float4*)s_in;
        float4 xv[4];
        #pragma unroll
        for (int t = 0; t < 4; t++) xv[t] = in4[lane + 32 * t];
        const int r = bid * NWARP + wid;
        const float4* w4 = (const float4*)(attn_w + (size_t)r * H2);
        float4 A[4];
        #pragma unroll
        for (int t = 0; t < 4; t++) A[t] = __ldg(w4 + lane + 32 * t);
        float d = 0.f;
        #pragma unroll
        for (int t = 0; t < 4; t++) d += dot4f(A[t], xv[t]);
        d = wredsum(d);
        if (lane == 0) g_attn_logits[r] = d + __ldg(attn_b + r);
    } else {
        int W = (bid - 16) * NWARP + wid;
        int l = W >> 8, j = W & 255;
        const float* whh = gru_whh + (size_t)l * 3 * H * H;
        const float4* h4 = (const float4*)(hidden + l * H);
        float4 ha = __ldg(h4 + lane), hb = __ldg(h4 + lane + 32);
        const float4* wr = (const float4*)(whh + (size_t)j * H);
        const float4* wz = (const float4*)(whh + (size_t)(H + j) * H);
        const float4* wn = (const float4*)(whh + (size_t)(2 * H + j) * H);
        float4 W0 = __ldg(wr + lane), W1 = __ldg(wr + lane + 32);
        float4 W2 = __ldg(wz + lane), W3 = __ldg(wz + lane + 32);
        float4 W4 = __ldg(wn + lane), W5 = __ldg(wn + lane + 32);
        float dr = dot4f(W0, ha) + dot4f(W1, hb);
        float dz = dot4f(W2, ha) + dot4f(W3, hb);
        float dn = dot4f(W4, ha) + dot4f(W5, hb);
        float v = red4(dr, dz, dn, 0.f, lane);
        int part = lane >> 3;
        if ((lane & 7) == 0 && part < 3)
            g_gh[(l * 3 + part) * H + j] = v + __ldg(gru_bhh + (l * 3 + part) * H + j);
    }
    __threadfence();
    pdl_trigger();
}

// ====== K2: softmax + attn_applied + comb (grid 16) ========================
__global__ void __launch_bounds__(TPB, 1)
k_attn_comb(const int* __restrict__ token,
            const float* __restrict__ enc,
            const float* __restrict__ emb,
            const float* __restrict__ comb_w,
            const float* __restrict__ comb_b,
            float* __restrict__ out)
{
    const int tid = threadIdx.x, bid = blockIdx.x;
    const int wid = tid >> 5, lane = tid & 31;
    __shared__ __align__(16) float s_in[H2];
    __shared__ __align__(16) float s_aw[SEQ];
    __shared__ __align__(16) float s_part[NWARP][H];
    __shared__ float s_red[NWARP];
    __shared__ float s_bc[2];

    // ---- x-independent prologue: comb weights + comb bias + emb row --------
    const int j = bid * NWARP + wid;
    const float4* w4 = (const float4*)(comb_w + (size_t)j * H2);
    float4 A[4];
    #pragma unroll
    for (int t = 0; t < 4; t++) A[t] = __ldg(w4 + lane + 32 * t);
    float cbias = __ldg(comb_b + j);
    {
        const int tok = token[0];
        const float* erow = emb + (size_t)tok * H;
        if (tid < H) s_in[tid] = __ldg(erow + tid);
    }
    pdl_wait();

    // ---- softmax over logits (redundant per block) ----
    float v = (tid < SEQ) ? g_attn_logits[tid] : -1e30f;
    float wm = v;
    #pragma unroll
    for (int o = 16; o; o >>= 1) wm = fmaxf(wm, __shfl_xor_sync(0xffffffffu, wm, o));
    if (lane == 0) s_red[wid] = wm;
    __syncthreads();
    if (tid == 0) {
        float m = s_red[0];
        #pragma unroll
        for (int w = 1; w < NWARP; w++) m = fmaxf(m, s_red[w]);
        s_bc[0] = m;
    }
    __syncthreads();
    float ex = (tid < SEQ) ? expf(v - s_bc[0]) : 0.f;
    float ws = ex;
    #pragma unroll
    for (int o = 16; o; o >>= 1) ws += __shfl_xor_sync(0xffffffffu, ws, o);
    if (lane == 0) s_red[wid] = ws;
    __syncthreads();
    if (tid == 0) {
        float s = 0.f;
        #pragma unroll
        for (int w = 0; w < NWARP; w++) s += s_red[w];
        s_bc[1] = s;
    }
    __syncthreads();
    float aw = ex / s_bc[1];
    if (tid < SEQ) s_aw[tid] = aw;
    __syncthreads();

    // ---- attn_applied: warp w covers seq [16w,16w+16), lanes cover columns
    {
        float acc[8];
        #pragma unroll
        for (int c8 = 0; c8 < 8; c8++) acc[c8] = 0.f;
        int i0 = wid * 16;
        #pragma unroll 4
        for (int ii = 0; ii < 16; ii++) {
            float a = s_aw[i0 + ii];
            const float* er = enc + (size_t)(i0 + ii) * H;
            #pragma unroll
            for (int c8 = 0; c8 < 8; c8++)
                acc[c8] = fmaf(a, __ldg(er + c8 * 32 + lane), acc[c8]);
        }
        #pragma unroll
        for (int c8 = 0; c8 < 8; c8++) s_part[wid][c8 * 32 + lane] = acc[c8];
    }
    __syncthreads();
    if (tid < H) {
        float ap = 0.f;
        #pragma unroll
        for (int w = 0; w < NWARP; w++) ap += s_part[w][tid];
        s_in[H + tid] = ap;
    }
    __syncthreads();

    // ---- comb: warp per row j (16 blocks x 16 warps = 256) ----
    {
        const float4* in4 = (const float4*)s_in;
        float4 xv[4];
        #pragma unroll
        for (int t = 0; t < 4; t++) xv[t] = in4[lane + 32 * t];
        float d = 0.f;
        #pragma unroll
        for (int t = 0; t < 4; t++) d += dot4f(A[t], xv[t]);
        d = wredsum(d);
        if (lane == 0) g_xbuf[0][j] = fmaxf(d + cbias, 0.f);
    }
    __threadfence();
    pdl_trigger();
    // attn_weights output (not needed by dependents)
    if (bid == 0 && tid < SEQ) out[VOC + NL * H + tid] = s_aw[tid];
}

// ====================== K3: one GRU layer (grid 16) =========================
__global__ void __launch_bounds__(TPB, 1)
k_gru(const float* __restrict__ hidden,
      const float* __restrict__ gru_wih,
      const float* __restrict__ gru_bih,
      float* __restrict__ out, int l)
{
    const int tid = threadIdx.x, bid = blockIdx.x;
    const int wid = tid >> 5, lane = tid & 31;
    __shared__ __align__(16) float s_x[H];

    // ---- x-independent prologue: weights + epilogue scalars ---------------
    const int j = bid * NWARP + wid;
    const float* wih = gru_wih + (size_t)l * 3 * H * H;
    const float4* wr = (const float4*)(wih + (size_t)j * H);
    const float4* wz = (const float4*)(wih + (size_t)(H + j) * H);
    const float4* wn = (const float4*)(wih + (size_t)(2 * H + j) * H);
    float4 W0 = __ldg(wr + lane), W1 = __ldg(wr + lane + 32);
    float4 W2 = __ldg(wz + lane), W3 = __ldg(wz + lane + 32);
    float4 W4 = __ldg(wn + lane), W5 = __ldg(wn + lane + 32);
    float p_ghr = g_gh[(l * 3 + 0) * H + j];
    float p_ghz = g_gh[(l * 3 + 1) * H + j];
    float p_ghn = g_gh[(l * 3 + 2) * H + j];
    float p_br  = __ldg(gru_bih + (l * 3 + 0) * H + j);
    float p_bz  = __ldg(gru_bih + (l * 3 + 1) * H + j);
    float p_bn  = __ldg(gru_bih + (l * 3 + 2) * H + j);
    float p_h   = __ldg(hidden + l * H + j);
    pdl_wait();

    if (tid < H) s_x[tid] = g_xbuf[l & 1][tid];
    __syncthreads();
    const float4* x4 = (const float4*)s_x;
    float4 xa = x4[lane], xb = x4[lane + 32];
    float dr = dot4f(W0, xa) + dot4f(W1, xb);
    float dz = dot4f(W2, xa) + dot4f(W3, xb);
    float dn = dot4f(W4, xa) + dot4f(W5, xb);
    float v = red4(dr, dz, dn, 0.f, lane);
    float rs = __shfl_sync(0xffffffffu, v, 0);
    float zs = __shfl_sync(0xffffffffu, v, 8);
    float ns = __shfl_sync(0xffffffffu, v, 16);
    float hnew = 0.f;
    if (lane == 0) {
        float r = 1.f / (1.f + expf(-((rs + p_br) + p_ghr)));
        float z = 1.f / (1.f + expf(-((zs + p_bz) + p_ghz)));
        float n = tanhf((ns + p_bn) + r * p_ghn);
        hnew = (1.f - z) * n + z * p_h;
        g_xbuf[(l + 1) & 1][j] = hnew;
    }
    __threadfence();
    pdl_trigger();
    if (lane == 0) out[VOC + l * H + j] = hnew;   // hidden_new output
}

// ========== K4: GEMV + streaming lse + merged finalize (grid 148) ===========
__global__ void __launch_bounds__(TPB, 1)
k_gemv(const float* __restrict__ out_w,
       const float* __restrict__ out_b,
       float* __restrict__ out)
{
    const int tid = threadIdx.x, bid = blockIdx.x;
    const int wid = tid >> 5, lane = tid & 31;
    __shared__ __align__(16) float s_x[H];
    __shared__ float s_ms[2 * NWARP];
    __shared__ float s_lse;
    __shared__ unsigned s_e;

    if (tid == 0) s_e = *(volatile unsigned*)&g_f4[bid];  // owner-only epoch
    __syncthreads();
    const unsigned e = s_e;

    const int gwid = bid * NWARP + wid;
    const int rown = lane >> 2;
    const bool own = (lane & 3) == 0;

    // ---- x-independent prologue: iteration-0 tiles + bias (PDL-hidden) -----
    float4 A0[16];
    {
        int r0 = gwid * 8;
        #pragma unroll
        for (int i = 0; i < 8; i++) {
            int row = r0 + i; if (row > VOC - 1) row = VOC - 1;
            const float4* wr = (const float4*)(out_w + (size_t)row * H);
            A0[2 * i]     = __ldg(wr + lane);
            A0[2 * i + 1] = __ldg(wr + lane + 32);
        }
    }
    float bias0 = 0.f;
    {
        int myrow = gwid * 8 + rown;
        if (own && myrow < VOC) bias0 = __ldg(out_b + myrow);
    }
    pdl_wait();

    if (tid < H) s_x[tid] = g_xbuf[0][tid];   // NL even -> buf 0
    __syncthreads();
    const float4* x4 = (const float4*)s_x;
    float4 xa = x4[lane], xb = x4[lane + 32];
    float mM = -1e30f, sS = 0.f;
    float vsave[GEMV_ITERS];

    // ---- iteration 0 from preloaded tiles ----------------------------------
    {
        int r0 = gwid * 8;
        int myrow = r0 + rown;
        float d[8];
        #pragma unroll
        for (int i = 0; i < 8; i++)
            d[i] = dot4f(A0[2 * i], xa) + dot4f(A0[2 * i + 1], xb);
        float v = red8(d, lane);
        if (own && myrow < VOC) {
            v += bias0;
            vsave[0] = v;
            float m2 = fmaxf(mM, v);
            sS = sS * expf(mM - m2) + expf(v - m2);
            mM = m2;
        }
    }
    // ---- iterations 1..2 ----------------------------------------------------
    #pragma unroll 1
    for (int it = 1; it < GEMV_ITERS; it++) {
        int r0 = (it * GEMV_TOTW + gwid) * 8;
        int myrow = r0 + rown;
        float bias = (own && myrow < VOC) ? __ldg(out_b + myrow) : 0.f;
        float d[8];
        #pragma unroll
        for (int i = 0; i < 8; i++) {
            int row = r0 + i;
            float s = 0.f;
            if (row < VOC) {
                const float4* wr = (const float4*)(out_w + (size_t)row * H);
                float4 a0 = __ldg(wr + lane), a1 = __ldg(wr + lane + 32);
                s = dot4f(a0, xa) + dot4f(a1, xb);
            }
            d[i] = s;
        }
        float v = red8(d, lane);
        if (own && myrow < VOC) {
            v += bias;
            vsave[it] = v;
            float m2 = fmaxf(mM, v);
            sS = sS * expf(mM - m2) + expf(v - m2);
            mM = m2;
        }
    }
    // ---- block (m,s) ----
    #pragma unroll
    for (int o = 16; o; o >>= 1) {
        float om = __shfl_xor_sync(0xffffffffu, mM, o);
        float os = __shfl_xor_sync(0xffffffffu, sS, o);
        float m2 = fmaxf(mM, om);
        sS = sS * expf(mM - m2) + os * expf(om - m2);
        mM = m2;
    }
    if (lane == 0) { s_ms[wid] = mM; s_ms[NWARP + wid] = sS; }
    __syncthreads();
    if (tid == 0) {
        float M = s_ms[0], S = s_ms[NWARP];
        #pragma unroll
        for (int w = 1; w < NWARP; w++) {
            float m2 = fmaxf(M, s_ms[w]);
            S = S * expf(M - m2) + s_ms[NWARP + w] * expf(s_ms[w] - m2);
            M = m2;
        }
        __stcg(&g_red[bid], make_float2(M, S));
        __threadfence();
        *(volatile unsigned*)&g_f4[bid] = e + 1u;
    }
    // ---- one-hop all-to-all wait (covers gemv finish spread only) ----------
    if (tid < GEMV_GRID) {
        while (*(volatile unsigned*)&g_f4[tid] < e + 1u) { __nanosleep(32); }
    }
    __syncthreads();
    __threadfence();
    // ---- redundant lse ----
    if (wid == 0) {
        float M = -1e30f, S = 0.f;
        for (int k = lane; k < GEMV_GRID; k += 32) {
            float2 p = __ldcg(&g_red[k]);
            float m2 = fmaxf(M, p.x);
            S = S * expf(M - m2) + p.y * expf(p.x - m2);
            M = m2;
        }
        #pragma unroll
        for (int o = 16; o; o >>= 1) {
            float om = __shfl_xor_sync(0xffffffffu, M, o);
            float os = __shfl_xor_sync(0xffffffffu, S, o);
            float m2 = fmaxf(M, om);
            S = S * expf(M - m2) + os * expf(om - m2);
            M = m2;
        }
        if (lane == 0) s_lse = M + logf(S);
    }
    __syncthreads();
    float lse = s_lse;
    // ---- single write of final log-probs from registers --------------------
    if (own) {
        #pragma unroll
        for (int it = 0; it < GEMV_ITERS; it++) {
            int row = (it * GEMV_TOTW + gwid) * 8 + rown;
            if (row < VOC) out[row] = vsave[it] - lse;
        }
    }
}

// ---------------- host: PDL launch helper -----------------------------------
static void launch_pdl(const void* func, dim3 grid, dim3 block, void** args) {
    cudaLaunchConfig_t cfg = {};
    cfg.gridDim = grid;
    cfg.blockDim = block;
    cfg.dynamicSmemBytes = 0;
    cfg.stream = 0;
    cudaLaunchAttribute attr[1];
    attr[0].id = cudaLaunchAttributeProgrammaticStreamSerialization;
    attr[0].val.programmaticStreamSerializationAllowed = 1;
    cfg.attrs = attr;
    cfg.numAttrs = 1;
    cudaLaunchKernelExC(&cfg, func, args);
}

extern "C" void kernel_launch(void* const* d_in, const int* in_sizes, int n_in,
                              void* d_out, int out_size) {
    const int*   token   = (const int*)d_in[0];
    const float* hidden  = (const float*)d_in[1];
    const float* enc     = (const float*)d_in[2];
    const float* emb     = (const float*)d_in[3];
    const float* attn_w  = (const float*)d_in[4];
    const float* attn_b  = (const float*)d_in[5];
    const float* comb_w  = (const float*)d_in[6];
    const float* comb_b  = (const float*)d_in[7];
    const float* gru_wih = (const float*)d_in[8];
    const float* gru_whh = (const float*)d_in[9];
    const float* gru_bih = (const float*)d_in[10];
    const float* gru_bhh = (const float*)d_in[11];
    const float* out_w   = (const float*)d_in[12];
    const float* out_b   = (const float*)d_in[13];
    float* out = (float*)d_out;

    k_logits_gh<<<80, TPB>>>(token, hidden, emb, attn_w, attn_b, gru_whh, gru_bhh);
    {
        void* a[] = {(void*)&token, (void*)&enc, (void*)&emb, (void*)&comb_w,
                     (void*)&comb_b, (void*)&out};
        launch_pdl((const void*)k_attn_comb, dim3(16), dim3(TPB), a);
    }
    static int ls[NL] = {0, 1, 2, 3};
    for (int l = 0; l < NL; l++) {
        void* a[] = {(void*)&hidden, (void*)&gru_wih, (void*)&gru_bih,
                     (void*)&out, (void*)&ls[l]};
        launch_pdl((const void*)k_gru, dim3(16), dim3(TPB), a);
    }
    {
        void* a[] = {(void*)&out_w, (void*)&out_b, (void*)&out};
        launch_pdl((const void*)k_gemv, dim3(GEMV_GRID), dim3(TPB), a);
    }
}

// round 16
// speedup vs baseline: 1.1981x; 1.1981x over previous
#include <cuda_runtime.h>
#include <math.h>

#define H    256
#define H2   512
#define SEQ  256
#define NL   4
#define VOC  50257
#define TPB  512
#define NWARP 16

#define GEMV_GRID 148
#define GEMV_TOTW (GEMV_GRID * NWARP)   // 2368
#define GEMV_ITERS 3                    // 3*2368*8 = 56832 >= VOC

// ---------------- scratch (device globals; no allocation allowed) ----------
__device__ __align__(16) float  g_attn_logits[SEQ];
__device__ __align__(16) float  g_xbuf[2][H];
__device__ __align__(16) float2 g_red[GEMV_GRID];

// ---------------- PDL helpers -----------------------------------------------
__device__ __forceinline__ void pdl_wait() {
    asm volatile("griddepcontrol.wait;" ::: "memory");
}
__device__ __forceinline__ void pdl_trigger() {
    asm volatile("griddepcontrol.launch_dependents;" ::: "memory");
}

// ---------------- math helpers ----------------------------------------------
__device__ __forceinline__ float dot4f(float4 a, float4 b) {
    return fmaf(a.x, b.x, fmaf(a.y, b.y, fmaf(a.z, b.z, a.w * b.w)));
}
__device__ __forceinline__ float wredsum(float v) {
    #pragma unroll
    for (int o = 16; o; o >>= 1) v += __shfl_xor_sync(0xffffffffu, v, o);
    return v;
}
// packed 4-row warp reduce: lanes 0-7 hold full sum of d0, 8-15 d1, 16-23 d2,
// 24-31 d3.
__device__ __forceinline__ float red4(float d0, float d1, float d2, float d3, int lane) {
    bool h16 = (lane & 16) != 0, h8 = (lane & 8) != 0;
    float k0 = (h16 ? d2 : d0) + __shfl_xor_sync(0xffffffffu, h16 ? d0 : d2, 16);
    float k1 = (h16 ? d3 : d1) + __shfl_xor_sync(0xffffffffu, h16 ? d1 : d3, 16);
    float v  = (h8 ? k1 : k0) + __shfl_xor_sync(0xffffffffu, h8 ? k0 : k1, 8);
    v += __shfl_xor_sync(0xffffffffu, v, 4);
    v += __shfl_xor_sync(0xffffffffu, v, 2);
    v += __shfl_xor_sync(0xffffffffu, v, 1);
    return v;
}
// packed 8-row warp reduce: every lane ends with full sum of row (lane>>2);
// owner = (lane&3)==0.
__device__ __forceinline__ float red8(const float* d, int lane) {
    bool h16 = (lane & 16) != 0, h8 = (lane & 8) != 0, h4b = (lane & 4) != 0;
    float k0 = (h16 ? d[4] : d[0]) + __shfl_xor_sync(0xffffffffu, h16 ? d[0] : d[4], 16);
    float k1 = (h16 ? d[5] : d[1]) + __shfl_xor_sync(0xffffffffu, h16 ? d[1] : d[5], 16);
    float k2 = (h16 ? d[6] : d[2]) + __shfl_xor_sync(0xffffffffu, h16 ? d[2] : d[6], 16);
    float k3 = (h16 ? d[7] : d[3]) + __shfl_xor_sync(0xffffffffu, h16 ? d[3] : d[7], 16);
    float m0 = (h8 ? k2 : k0) + __shfl_xor_sync(0xffffffffu, h8 ? k0 : k2, 8);
    float m1 = (h8 ? k3 : k1) + __shfl_xor_sync(0xffffffffu, h8 ? k1 : k3, 8);
    float v  = (h4b ? m1 : m0) + __shfl_xor_sync(0xffffffffu, h4b ? m0 : m1, 4);
    v += __shfl_xor_sync(0xffffffffu, v, 2);
    v += __shfl_xor_sync(0xffffffffu, v, 1);
    return v;
}

// ====================== K1: attention logits only (grid 16) =================
__global__ void __launch_bounds__(TPB, 1)
k_logits(const int* __restrict__ token,
         const float* __restrict__ hidden,
         const float* __restrict__ emb,
         const float* __restrict__ attn_w,
         const float* __restrict__ attn_b)
{
    const int tid = threadIdx.x, bid = blockIdx.x;
    const int wid = tid >> 5, lane = tid & 31;
    __shared__ __align__(16) float s_in[H2];

    const int tok = token[0];
    const float* erow = emb + (size_t)tok * H;
    s_in[tid] = (tid < H) ? __ldg(erow + tid) : __ldg(hidden + tid - H);
    __syncthreads();
    const float4* in4 = (const float4*)s_in;
    float4 xv[4];
    #pragma unroll
    for (int t = 0; t < 4; t++) xv[t] = in4[lane + 32 * t];
    const int r = bid * NWARP + wid;
    const float4* w4 = (const float4*)(attn_w + (size_t)r * H2);
    float4 A[4];
    #pragma unroll
    for (int t = 0; t < 4; t++) A[t] = __ldg(w4 + lane + 32 * t);
    float d = 0.f;
    #pragma unroll
    for (int t = 0; t < 4; t++) d += dot4f(A[t], xv[t]);
    d = wredsum(d);
    if (lane == 0) g_attn_logits[r] = d + __ldg(attn_b + r);
    __threadfence();
    pdl_trigger();
}

// ====== K2: softmax + attn_applied + comb (grid 16) ========================
__global__ void __launch_bounds__(TPB, 1)
k_attn_comb(const int* __restrict__ token,
            const float* __restrict__ enc,
            const float* __restrict__ emb,
            const float* __restrict__ comb_w,
            const float* __restrict__ comb_b,
            float* __restrict__ out)
{
    const int tid = threadIdx.x, bid = blockIdx.x;
    const int wid = tid >> 5, lane = tid & 31;
    __shared__ __align__(16) float s_in[H2];
    __shared__ __align__(16) float s_aw[SEQ];
    __shared__ __align__(16) float s_part[NWARP][H];
    __shared__ float s_red[NWARP];
    __shared__ float s_bc[2];

    // ---- x-independent prologue: comb weights + comb bias + emb row --------
    const int j = bid * NWARP + wid;
    const float4* w4 = (const float4*)(comb_w + (size_t)j * H2);
    float4 A[4];
    #pragma unroll
    for (int t = 0; t < 4; t++) A[t] = __ldg(w4 + lane + 32 * t);
    float cbias = __ldg(comb_b + j);
    {
        const int tok = token[0];
        const float* erow = emb + (size_t)tok * H;
        if (tid < H) s_in[tid] = __ldg(erow + tid);
    }
    pdl_wait();

    // ---- softmax over logits (redundant per block) ----
    float v = (tid < SEQ) ? g_attn_logits[tid] : -1e30f;
    float wm = v;
    #pragma unroll
    for (int o = 16; o; o >>= 1) wm = fmaxf(wm, __shfl_xor_sync(0xffffffffu, wm, o));
    if (lane == 0) s_red[wid] = wm;
    __syncthreads();
    if (tid == 0) {
        float m = s_red[0];
        #pragma unroll
        for (int w = 1; w < NWARP; w++) m = fmaxf(m, s_red[w]);
        s_bc[0] = m;
    }
    __syncthreads();
    float ex = (tid < SEQ) ? expf(v - s_bc[0]) : 0.f;
    float ws = ex;
    #pragma unroll
    for (int o = 16; o; o >>= 1) ws += __shfl_xor_sync(0xffffffffu, ws, o);
    if (lane == 0) s_red[wid] = ws;
    __syncthreads();
    if (tid == 0) {
        float s = 0.f;
        #pragma unroll
        for (int w = 0; w < NWARP; w++) s += s_red[w];
        s_bc[1] = s;
    }
    __syncthreads();
    float aw = ex / s_bc[1];
    if (tid < SEQ) s_aw[tid] = aw;
    __syncthreads();

    // ---- attn_applied: warp w covers seq [16w,16w+16), lanes cover columns
    {
        float acc[8];
        #pragma unroll
        for (int c8 = 0; c8 < 8; c8++) acc[c8] = 0.f;
        int i0 = wid * 16;
        #pragma unroll 4
        for (int ii = 0; ii < 16; ii++) {
            float a = s_aw[i0 + ii];
            const float* er = enc + (size_t)(i0 + ii) * H;
            #pragma unroll
            for (int c8 = 0; c8 < 8; c8++)
                acc[c8] = fmaf(a, __ldg(er + c8 * 32 + lane), acc[c8]);
        }
        #pragma unroll
        for (int c8 = 0; c8 < 8; c8++) s_part[wid][c8 * 32 + lane] = acc[c8];
    }
    __syncthreads();
    if (tid < H) {
        float ap = 0.f;
        #pragma unroll
        for (int w = 0; w < NWARP; w++) ap += s_part[w][tid];
        s_in[H + tid] = ap;
    }
    __syncthreads();

    // ---- comb: warp per row j (16 blocks x 16 warps = 256) ----
    {
        const float4* in4 = (const float4*)s_in;
        float4 xv[4];
        #pragma unroll
        for (int t = 0; t < 4; t++) xv[t] = in4[lane + 32 * t];
        float d = 0.f;
        #pragma unroll
        for (int t = 0; t < 4; t++) d += dot4f(A[t], xv[t]);
        d = wredsum(d);
        if (lane == 0) g_xbuf[0][j] = fmaxf(d + cbias, 0.f);
    }
    __threadfence();
    pdl_trigger();
    // attn_weights output (not needed by dependents)
    if (bid == 0 && tid < SEQ) out[VOC + NL * H + tid] = s_aw[tid];
}

// ====================== K3: one GRU layer (grid 16) =========================
// gh = h @ whh.T + bhh is computed HERE, in the PDL-hidden prologue
// (x-independent: depends only on input hidden + whh/bhh).
__global__ void __launch_bounds__(TPB, 1)
k_gru(const float* __restrict__ hidden,
      const float* __restrict__ gru_wih,
      const float* __restrict__ gru_whh,
      const float* __restrict__ gru_bih,
      const float* __restrict__ gru_bhh,
      float* __restrict__ out, int l)
{
    const int tid = threadIdx.x, bid = blockIdx.x;
    const int wid = tid >> 5, lane = tid & 31;
    __shared__ __align__(16) float s_x[H];

    const int j = bid * NWARP + wid;

    // ---- prologue phase 1: gh for this warp's row j ------------------------
    float p_ghr, p_ghz, p_ghn;
    {
        const float* whh = gru_whh + (size_t)l * 3 * H * H;
        const float4* h4 = (const float4*)(hidden + l * H);
        float4 ha = __ldg(h4 + lane), hb = __ldg(h4 + lane + 32);
        const float4* vr = (const float4*)(whh + (size_t)j * H);
        const float4* vz = (const float4*)(whh + (size_t)(H + j) * H);
        const float4* vn = (const float4*)(whh + (size_t)(2 * H + j) * H);
        float4 V0 = __ldg(vr + lane), V1 = __ldg(vr + lane + 32);
        float4 V2 = __ldg(vz + lane), V3 = __ldg(vz + lane + 32);
        float4 V4 = __ldg(vn + lane), V5 = __ldg(vn + lane + 32);
        float hr = dot4f(V0, ha) + dot4f(V1, hb);
        float hz = dot4f(V2, ha) + dot4f(V3, hb);
        float hn = dot4f(V4, ha) + dot4f(V5, hb);
        float vg = red4(hr, hz, hn, 0.f, lane);
        p_ghr = __shfl_sync(0xffffffffu, vg, 0)  + __ldg(gru_bhh + (l * 3 + 0) * H + j);
        p_ghz = __shfl_sync(0xffffffffu, vg, 8)  + __ldg(gru_bhh + (l * 3 + 1) * H + j);
        p_ghn = __shfl_sync(0xffffffffu, vg, 16) + __ldg(gru_bhh + (l * 3 + 2) * H + j);
    }

    // ---- prologue phase 2: wih weights + epilogue scalars ------------------
    const float* wih = gru_wih + (size_t)l * 3 * H * H;
    const float4* wr = (const float4*)(wih + (size_t)j * H);
    const float4* wz = (const float4*)(wih + (size_t)(H + j) * H);
    const float4* wn = (const float4*)(wih + (size_t)(2 * H + j) * H);
    float4 W0 = __ldg(wr + lane), W1 = __ldg(wr + lane + 32);
    float4 W2 = __ldg(wz + lane), W3 = __ldg(wz + lane + 32);
    float4 W4 = __ldg(wn + lane), W5 = __ldg(wn + lane + 32);
    float p_br  = __ldg(gru_bih + (l * 3 + 0) * H + j);
    float p_bz  = __ldg(gru_bih + (l * 3 + 1) * H + j);
    float p_bn  = __ldg(gru_bih + (l * 3 + 2) * H + j);
    float p_h   = __ldg(hidden + l * H + j);
    pdl_wait();

    if (tid < H) s_x[tid] = g_xbuf[l & 1][tid];
    __syncthreads();
    const float4* x4 = (const float4*)s_x;
    float4 xa = x4[lane], xb = x4[lane + 32];
    float dr = dot4f(W0, xa) + dot4f(W1, xb);
    float dz = dot4f(W2, xa) + dot4f(W3, xb);
    float dn = dot4f(W4, xa) + dot4f(W5, xb);
    float v = red4(dr, dz, dn, 0.f, lane);
    float rs = __shfl_sync(0xffffffffu, v, 0);
    float zs = __shfl_sync(0xffffffffu, v, 8);
    float ns = __shfl_sync(0xffffffffu, v, 16);
    float hnew = 0.f;
    if (lane == 0) {
        float r = 1.f / (1.f + expf(-((rs + p_br) + p_ghr)));
        float z = 1.f / (1.f + expf(-((zs + p_bz) + p_ghz)));
        float n = tanhf((ns + p_bn) + r * p_ghn);
        hnew = (1.f - z) * n + z * p_h;
        g_xbuf[(l + 1) & 1][j] = hnew;
    }
    __threadfence();
    pdl_trigger();
    if (lane == 0) out[VOC + l * H + j] = hnew;   // hidden_new output
}

// ====================== K4: GEMV + per-block (m,s) (grid 148) ===============
__global__ void __launch_bounds__(TPB, 1)
k_gemv(const float* __restrict__ out_w,
       const float* __restrict__ out_b,
       float* __restrict__ out)
{
    const int tid = threadIdx.x, bid = blockIdx.x;
    const int wid = tid >> 5, lane = tid & 31;
    __shared__ __align__(16) float s_x[H];
    __shared__ float s_ms[2 * NWARP];

    const int gwid = bid * NWARP + wid;
    const int rown = lane >> 2;
    const bool own = (lane & 3) == 0;

    // ---- x-independent prologue: iteration-0 tiles + bias (PDL-hidden) -----
    float4 A0[16];
    {
        int r0 = gwid * 8;
        #pragma unroll
        for (int i = 0; i < 8; i++) {
            int row = r0 + i; if (row > VOC - 1) row = VOC - 1;
            const float4* wr = (const float4*)(out_w + (size_t)row * H);
            A0[2 * i]     = __ldg(wr + lane);
            A0[2 * i + 1] = __ldg(wr + lane + 32);
        }
    }
    float bias0 = 0.f;
    {
        int myrow = gwid * 8 + rown;
        if (own && myrow < VOC) bias0 = __ldg(out_b + myrow);
    }
    pdl_wait();

    if (tid < H) s_x[tid] = g_xbuf[0][tid];   // NL even -> buf 0
    __syncthreads();
    const float4* x4 = (const float4*)s_x;
    float4 xa = x4[lane], xb = x4[lane + 32];
    float mM = -1e30f, sS = 0.f;

    // ---- iteration 0 from preloaded tiles ----------------------------------
    {
        int r0 = gwid * 8;
        int myrow = r0 + rown;
        float d[8];
        #pragma unroll
        for (int i = 0; i < 8; i++)
            d[i] = dot4f(A0[2 * i], xa) + dot4f(A0[2 * i + 1], xb);
        float v = red8(d, lane);
        if (own && myrow < VOC) {
            v += bias0;
            out[myrow] = v;
            float m2 = fmaxf(mM, v);
            sS = sS * expf(mM - m2) + expf(v - m2);
            mM = m2;
        }
    }
    // ---- iterations 1..2 ----------------------------------------------------
    #pragma unroll 1
    for (int it = 1; it < GEMV_ITERS; it++) {
        int r0 = (it * GEMV_TOTW + gwid) * 8;
        int myrow = r0 + rown;
        float bias = (own && myrow < VOC) ? __ldg(out_b + myrow) : 0.f;
        float d[8];
        #pragma unroll
        for (int i = 0; i < 8; i++) {
            int row = r0 + i;
            float s = 0.f;
            if (row < VOC) {
                const float4* wr = (const float4*)(out_w + (size_t)row * H);
                float4 a0 = __ldg(wr + lane), a1 = __ldg(wr + lane + 32);
                s = dot4f(a0, xa) + dot4f(a1, xb);
            }
            d[i] = s;
        }
        float v = red8(d, lane);
        if (own && myrow < VOC) {
            v += bias;
            out[myrow] = v;
            float m2 = fmaxf(mM, v);
            sS = sS * expf(mM - m2) + expf(v - m2);
            mM = m2;
        }
    }
    #pragma unroll
    for (int o = 16; o; o >>= 1) {
        float om = __shfl_xor_sync(0xffffffffu, mM, o);
        float os = __shfl_xor_sync(0xffffffffu, sS, o);
        float m2 = fmaxf(mM, om);
        sS = sS * expf(mM - m2) + os * expf(om - m2);
        mM = m2;
    }
    if (lane == 0) { s_ms[wid] = mM; s_ms[NWARP + wid] = sS; }
    __syncthreads();
    if (tid == 0) {
        float M = s_ms[0], S = s_ms[NWARP];
        #pragma unroll
        for (int w = 1; w < NWARP; w++) {
            float m2 = fmaxf(M, s_ms[w]);
            S = S * expf(M - m2) + s_ms[NWARP + w] * expf(s_ms[w] - m2);
            M = m2;
        }
        g_red[bid] = make_float2(M, S);
    }
    __threadfence();
    pdl_trigger();
}

// ====================== K5: finalize lse + subtract (grid 148) ==============
__global__ void __launch_bounds__(TPB, 1)
k_final(float* __restrict__ out)
{
    const int tid = threadIdx.x, bid = blockIdx.x;
    const int wid = tid >> 5, lane = tid & 31;
    __shared__ float s_lse;

    pdl_wait();
    if (wid == 0) {
        float M = -1e30f, S = 0.f;
        for (int k = lane; k < GEMV_GRID; k += 32) {
            float2 p = g_red[k];
            float m2 = fmaxf(M, p.x);
            S = S * expf(M - m2) + p.y * expf(p.x - m2);
            M = m2;
        }
        #pragma unroll
        for (int o = 16; o; o >>= 1) {
            float om = __shfl_xor_sync(0xffffffffu, M, o);
            float os = __shfl_xor_sync(0xffffffffu, S, o);
            float m2 = fmaxf(M, om);
            S = S * expf(M - m2) + os * expf(om - m2);
            M = m2;
        }
        if (lane == 0) s_lse = M + logf(S);
    }
    __syncthreads();
    float lse = s_lse;
    int i = bid * TPB + tid;          // 148*512 = 75776 >= VOC, one pass
    if (i < VOC) out[i] -= lse;
}

// ---------------- host: PDL launch helper -----------------------------------
static void launch_pdl(const void* func, dim3 grid, dim3 block, void** args) {
    cudaLaunchConfig_t cfg = {};
    cfg.gridDim = grid;
    cfg.blockDim = block;
    cfg.dynamicSmemBytes = 0;
    cfg.stream = 0;
    cudaLaunchAttribute attr[1];
    attr[0].id = cudaLaunchAttributeProgrammaticStreamSerialization;
    attr[0].val.programmaticStreamSerializationAllowed = 1;
    cfg.attrs = attr;
    cfg.numAttrs = 1;
    cudaLaunchKernelExC(&cfg, func, args);
}

extern "C" void kernel_launch(void* const* d_in, const int* in_sizes, int n_in,
                              void* d_out, int out_size) {
    const int*   token   = (const int*)d_in[0];
    const float* hidden  = (const float*)d_in[1];
    const float* enc     = (const float*)d_in[2];
    const float* emb     = (const float*)d_in[3];
    const float* attn_w  = (const float*)d_in[4];
    const float* attn_b  = (const float*)d_in[5];
    const float* comb_w  = (const float*)d_in[6];
    const float* comb_b  = (const float*)d_in[7];
    const float* gru_wih = (const float*)d_in[8];
    const float* gru_whh = (const float*)d_in[9];
    const float* gru_bih = (const float*)d_in[10];
    const float* gru_bhh = (const float*)d_in[11];
    const float* out_w   = (const float*)d_in[12];
    const float* out_b   = (const float*)d_in[13];
    float* out = (float*)d_out;

    k_logits<<<16, TPB>>>(token, hidden, emb, attn_w, attn_b);
    {
        void* a[] = {(void*)&token, (void*)&enc, (void*)&emb, (void*)&comb_w,
                     (void*)&comb_b, (void*)&out};
        launch_pdl((const void*)k_attn_comb, dim3(16), dim3(TPB), a);
    }
    static int ls[NL] = {0, 1, 2, 3};
    for (int l = 0; l < NL; l++) {
        void* a[] = {(void*)&hidden, (void*)&gru_wih, (void*)&gru_whh,
                     (void*)&gru_bih, (void*)&gru_bhh, (void*)&out, (void*)&ls[l]};
        launch_pdl((const void*)k_gru, dim3(16), dim3(TPB), a);
    }
    {
        void* a[] = {(void*)&out_w, (void*)&out_b, (void*)&out};
        launch_pdl((const void*)k_gemv, dim3(GEMV_GRID), dim3(TPB), a);
    }
    {
        void* a[] = {(void*)&out};
        launch_pdl((const void*)k_final, dim3(GEMV_GRID), dim3(TPB), a);
    }
}